// round 11
// baseline (speedup 1.0000x reference)
#include <cuda_runtime.h>

#define B_ 64
#define T_ 800
#define J_ 50
#define D_ 200

constexpr int TPB1 = 256;
constexpr int NW   = 8;          // warps per block
constexpr int TT   = 4;          // t-rows per warp (phase B / softmax)
constexpr int TP   = 8;          // t-rows per warp pair (c2q)
constexpr int TBLK = NW * TT;    // 32 t-rows per block
constexpr int UPITCH4 = 51;      // float4 per u row (204 words; conflict-free)
constexpr int D4 = D_ / 4;       // 50
constexpr int KH = 25;           // d4-chunks per half (c2q split)
constexpr int NCHUNK = 25;       // = T_/TBLK
constexpr int ATP2 = 10;         // a_T pitch in float2 (80B rows: 16B-aligned, 4-way STS)

// scratch (no cudaMalloc allowed)
__device__ float2 g_cm[B_ * NCHUNK];            // (chunk max, chunk expsum)
__device__ float  g_part[B_ * NCHUNK * D_];     // unnormalized q2c partials
__device__ __align__(16) float g_q2c[B_ * D_];  // combined q2c

// ---- packed f32x2 helpers ----
__device__ __forceinline__ void fma2(unsigned long long& d, unsigned long long a, unsigned long long b) {
    asm("fma.rn.f32x2 %0, %1, %2, %0;" : "+l"(d) : "l"(a), "l"(b));
}
__device__ __forceinline__ float2 unpack2(unsigned long long v) {
    float2 r; asm("mov.b64 {%0, %1}, %2;" : "=f"(r.x), "=f"(r.y) : "l"(v)); return r;
}
__device__ __forceinline__ float warpSum(float v) {
    #pragma unroll
    for (int o = 16; o > 0; o >>= 1) v += __shfl_xor_sync(0xffffffffu, v, o);
    return v;
}
__device__ __forceinline__ float warpMax(float v) {
    #pragma unroll
    for (int o = 16; o > 0; o >>= 1) v = fmaxf(v, __shfl_xor_sync(0xffffffffu, v, o));
    return v;
}
__device__ __forceinline__ void barPair(int p) {
    asm volatile("bar.sync %0, 64;" :: "r"(p + 1) : "memory");
}

// =====================================================================
// K1: per (b, 32 t-rows): s row (warp-private, 4 rows, full d), softmax,
// c2q pair-split by d-half reading PRE-DUPLICATED a_T (zero ALU movs),
// out[:,0:600], plus chunk-local q2c partial.
// smem: u_s 40800 + hw_s 25600 + su 208 + m/es 256 = 66.9KB -> 3 CTAs/SM
// =====================================================================
__global__ __launch_bounds__(TPB1, 3) void bidaf_k1(
    const float* __restrict__ h, const float* __restrict__ u,
    const float* __restrict__ w_h, const float* __restrict__ b_h,
    const float* __restrict__ w_u, const float* __restrict__ b_u,
    const float* __restrict__ w_hu, const float* __restrict__ b_hu,
    float* __restrict__ out)
{
    extern __shared__ char smem_raw[];
    float* u_s  = (float*)smem_raw;                  // 50*204
    float* hw_s = u_s + J_ * UPITCH4 * 4;            // 32*200 (a_T overlays)
    float* su_s = hw_s + TBLK * D_;                  // 50 (+2 pad)
    float* m_s  = su_s + J_ + 2;                     // 32
    float* es_s = m_s + TBLK;                        // 32

    const int b    = blockIdx.y;
    const int c    = blockIdx.x;
    const int t0   = c * TBLK;
    const int tid  = threadIdx.x;
    const int warp = tid >> 5, lane = tid & 31;
    const int pair = warp >> 1, half = warp & 1;

    const float4* u4g = (const float4*)u;
    const float4* h4g = (const float4*)h;
    float4* us4 = (float4*)u_s;

    // ---- load u[b] tile into smem ----
    for (int idx = tid; idx < J_ * UPITCH4; idx += TPB1) {
        int j = idx / UPITCH4, k = idx - j * UPITCH4;
        if (k < D4) us4[j * UPITCH4 + k] = u4g[(b * J_ + j) * D4 + k];
    }
    const float bias = b_h[0] + b_u[0] + b_hu[0];
    __syncthreads();

    // ---- su_s[j] = dot(u_j, w_u) + bias ----
    const float4* wu4 = (const float4*)w_u;
    for (int j = warp; j < J_; j += NW) {
        float acc = 0.f;
        for (int k = lane; k < D4; k += 32) {
            float4 a = us4[j * UPITCH4 + k], w = wu4[k];
            acc += a.x * w.x + a.y * w.y + a.z * w.z + a.w * w.w;
        }
        acc = warpSum(acc);
        if (lane == 0) su_s[j] = acc + bias;
    }
    __syncthreads();

    // ---- phase A: hw = h * w_hu (to smem), sh = dot(h, w_h) ----
    const float4* whu4 = (const float4*)w_hu;
    const float4* wh4  = (const float4*)w_h;
    float4* hw4 = (float4*)hw_s + warp * (TT * D4);
    const int tw = t0 + warp * TT;
    float sh[TT];
    #pragma unroll
    for (int tt = 0; tt < TT; tt++) {
        long rb = (long)(b * T_ + tw + tt) * D4;
        float4 a = h4g[rb + lane];
        float4 w1 = whu4[lane];
        hw4[tt * D4 + lane] =
            make_float4(a.x * w1.x, a.y * w1.y, a.z * w1.z, a.w * w1.w);
        float4 w2 = wh4[lane];
        float p = a.x * w2.x + a.y * w2.y + a.z * w2.z + a.w * w2.w;
        if (lane < D4 - 32) {
            float4 a2 = h4g[rb + 32 + lane];
            float4 w1b = whu4[32 + lane];
            hw4[tt * D4 + 32 + lane] =
                make_float4(a2.x * w1b.x, a2.y * w1b.y, a2.z * w1b.z, a2.w * w1b.w);
            float4 w2b = wh4[32 + lane];
            p += a2.x * w2b.x + a2.y * w2b.y + a2.z * w2b.z + a2.w * w2b.w;
        }
        sh[tt] = warpSum(p);
    }
    __syncwarp();

    // ---- phase B (round-7 style): s[t,j] over full d, own 4 rows ----
    const bool jv = (lane < J_ - 32);
    unsigned long long acc[TT][2];
    #pragma unroll
    for (int tt = 0; tt < TT; tt++) { acc[tt][0] = 0ull; acc[tt][1] = 0ull; }

    const ulonglong2* usU = (const ulonglong2*)u_s;
    const ulonglong2* hwW = (const ulonglong2*)hw_s + warp * (TT * D4);
    const int j0 = lane, j1 = lane + 32;
    const ulonglong2* uj0 = usU + j0 * UPITCH4;
    const ulonglong2* uj1 = usU + j1 * UPITCH4;

    #pragma unroll 2
    for (int k = 0; k < D4; k++) {
        ulonglong2 U0 = uj0[k];
        ulonglong2 U1; U1.x = 0ull; U1.y = 0ull;
        if (jv) U1 = uj1[k];
        #pragma unroll
        for (int tt = 0; tt < TT; tt++) {
            ulonglong2 Hb = hwW[tt * D4 + k];  // broadcast
            fma2(acc[tt][0], U0.x, Hb.x);
            fma2(acc[tt][0], U0.y, Hb.y);
            fma2(acc[tt][1], U1.x, Hb.x);
            fma2(acc[tt][1], U1.y, Hb.y);
        }
    }
    // partner may still be reading its hw rows; a_T overlays pair region
    barPair(pair);

    // ---- softmax (own 4 rows); a_T stored PRE-DUPLICATED float2, pitch 10 ----
    float2* aT2 = (float2*)(hw_s + pair * (TP * D_));   // pair-local overlay
    const float su0 = su_s[j0];
    const float su1 = jv ? su_s[j1] : -1e30f;
    #pragma unroll
    for (int tt = 0; tt < TT; tt++) {
        const int r = half * TT + tt;
        float2 p0 = unpack2(acc[tt][0]);
        float2 p1 = unpack2(acc[tt][1]);
        float s0 = p0.x + p0.y + sh[tt] + su0;
        float s1 = p1.x + p1.y + sh[tt] + su1;
        float mx = warpMax(fmaxf(s0, s1));
        float e0 = __expf(s0 - mx);
        float e1 = __expf(s1 - mx);
        float sm = warpSum(e0 + e1);
        float inv = 1.f / sm;
        float a0 = e0 * inv, a1 = e1 * inv;
        aT2[j0 * ATP2 + r] = make_float2(a0, a0);
        if (jv) aT2[j1 * ATP2 + r] = make_float2(a1, a1);
        if (lane == 0) m_s[pair * TP + r] = mx;
    }
    barPair(pair);

    // ---- c2q pair-split: this warp's d-half, all 8 pair rows ----
    // per j: 1 U load + 4 LDS.128 broadcasts (packed (a,a) u64 pairs) + 16 fma2
    unsigned long long cacc[TP][2];
    #pragma unroll
    for (int r = 0; r < TP; r++) { cacc[r][0] = 0ull; cacc[r][1] = 0ull; }

    const bool kvalid = (lane < KH);
    const int myk = half * KH + lane;            // this lane's d4 chunk
    const ulonglong2* ukp = usU + (kvalid ? myk : 0);
    const ulonglong2* aU = (const ulonglong2*)aT2;   // 16B-aligned rows

    #pragma unroll 2
    for (int j = 0; j < J_; j++) {
        ulonglong2 Ua; Ua.x = 0ull; Ua.y = 0ull;
        if (kvalid) Ua = ukp[j * UPITCH4];
        const ulonglong2* aj = aU + j * (ATP2 / 2);  // j*5 ulonglong2
        ulonglong2 A01 = aj[0];    // rows 0,1 packed (a,a)
        ulonglong2 A23 = aj[1];    // rows 2,3
        ulonglong2 A45 = aj[2];    // rows 4,5
        ulonglong2 A67 = aj[3];    // rows 6,7
        fma2(cacc[0][0], A01.x, Ua.x); fma2(cacc[0][1], A01.x, Ua.y);
        fma2(cacc[1][0], A01.y, Ua.x); fma2(cacc[1][1], A01.y, Ua.y);
        fma2(cacc[2][0], A23.x, Ua.x); fma2(cacc[2][1], A23.x, Ua.y);
        fma2(cacc[3][0], A23.y, Ua.x); fma2(cacc[3][1], A23.y, Ua.y);
        fma2(cacc[4][0], A45.x, Ua.x); fma2(cacc[4][1], A45.x, Ua.y);
        fma2(cacc[5][0], A45.y, Ua.x); fma2(cacc[5][1], A45.y, Ua.y);
        fma2(cacc[6][0], A67.x, Ua.x); fma2(cacc[6][1], A67.x, Ua.y);
        fma2(cacc[7][0], A67.y, Ua.x); fma2(cacc[7][1], A67.y, Ua.y);
    }

    // ---- epilogue: out[b,t, 0:200]=h, [200:400]=c2q, [400:600]=h*c2q ----
    if (kvalid) {
        #pragma unroll
        for (int r = 0; r < TP; r++) {
            int t = t0 + pair * TP + r;
            long rb = (long)(b * T_ + t) * D4;
            float4* o4 = (float4*)out + (long)(b * T_ + t) * (4 * D4);
            float4 ha = h4g[rb + myk];
            float2 ca = unpack2(cacc[r][0]);
            float2 cb = unpack2(cacc[r][1]);
            float4 c0 = make_float4(ca.x, ca.y, cb.x, cb.y);
            __stcs(o4 + myk, ha);
            __stcs(o4 + 50 + myk, c0);
            __stcs(o4 + 100 + myk,
                   make_float4(ha.x * c0.x, ha.y * c0.y, ha.z * c0.z, ha.w * c0.w));
        }
    }

    // ---- chunk-local q2c partial ----
    __syncthreads();
    if (warp == 0) {
        float mv = (lane < TBLK) ? m_s[lane] : -3.0e38f;
        float mc = warpMax(mv);
        float ev = (lane < TBLK) ? __expf(mv - mc) : 0.f;
        float sc = warpSum(ev);
        if (lane < TBLK) es_s[lane] = ev;
        if (lane == 0) g_cm[b * NCHUNK + c] = make_float2(mc, sc);
    }
    __syncthreads();
    if (tid < D_) {
        const float* hp = h + ((long)b * T_ + t0) * D_ + tid;
        float a0 = 0.f, a1 = 0.f, a2 = 0.f, a3 = 0.f;
        #pragma unroll
        for (int t = 0; t < TBLK; t += 4) {
            a0 += es_s[t]     * hp[t * D_];
            a1 += es_s[t + 1] * hp[(t + 1) * D_];
            a2 += es_s[t + 2] * hp[(t + 2) * D_];
            a3 += es_s[t + 3] * hp[(t + 3) * D_];
        }
        g_part[(b * NCHUNK + c) * D_ + tid] = (a0 + a1) + (a2 + a3);
    }
}

// =====================================================================
// K2: per-batch combine of chunk records -> g_q2c[b,:]
// =====================================================================
__global__ __launch_bounds__(256) void bidaf_k2()
{
    __shared__ float ws[32];
    __shared__ float Ss;
    const int b = blockIdx.x, tid = threadIdx.x;
    if (tid < 32) {
        float2 cm = (tid < NCHUNK) ? g_cm[b * NCHUNK + tid] : make_float2(-3.0e38f, 0.f);
        float M = warpMax(cm.x);
        float e = (tid < NCHUNK) ? __expf(cm.x - M) : 0.f;
        float S = warpSum(e * cm.y);
        ws[tid] = e;
        if (tid == 0) Ss = S;
    }
    __syncthreads();
    if (tid < D_) {
        float acc = 0.f;
        #pragma unroll
        for (int c2 = 0; c2 < NCHUNK; c2++)
            acc += ws[c2] * g_part[(b * NCHUNK + c2) * D_ + tid];
        g_q2c[b * D_ + tid] = acc / Ss;
    }
}

// =====================================================================
// K3: flat streaming: out[b,t,600:800] = h[b,t,:] * q2c[b,:]
// =====================================================================
__global__ __launch_bounds__(256) void bidaf_k3(const float* __restrict__ h,
                                                float* __restrict__ out)
{
    long idx = (long)blockIdx.x * 256 + threadIdx.x;   // float4 index
    if (idx >= (long)B_ * T_ * D4) return;
    int d4 = (int)(idx % D4);
    long bt = idx / D4;
    int b = (int)(bt / T_);
    float4 hv = __ldg(((const float4*)h) + idx);
    float4 q  = __ldg(((const float4*)g_q2c) + b * D4 + d4);
    __stcs(((float4*)out) + bt * (4 * D4) + 150 + d4,
           make_float4(hv.x * q.x, hv.y * q.y, hv.z * q.z, hv.w * q.w));
}

// =====================================================================
extern "C" void kernel_launch(void* const* d_in, const int* in_sizes, int n_in,
                              void* d_out, int out_size)
{
    const float* h    = (const float*)d_in[0];
    const float* u    = (const float*)d_in[1];
    const float* w_h  = (const float*)d_in[2];
    const float* b_h  = (const float*)d_in[3];
    const float* w_u  = (const float*)d_in[4];
    const float* b_u  = (const float*)d_in[5];
    const float* w_hu = (const float*)d_in[6];
    const float* b_hu = (const float*)d_in[7];
    float* out = (float*)d_out;

    constexpr int SMEM1 = (J_ * UPITCH4 * 4      // u_s
                         + TBLK * D_             // hw_s (a_T overlays)
                         + J_ + 2                // su_s
                         + 2 * TBLK) * 4;        // m_s + es_s
    cudaFuncSetAttribute(bidaf_k1, cudaFuncAttributeMaxDynamicSharedMemorySize, SMEM1);

    bidaf_k1<<<dim3(NCHUNK, B_), TPB1, SMEM1>>>(h, u, w_h, b_h, w_u, b_u, w_hu, b_hu, out);
    bidaf_k2<<<B_, 256>>>();
    int total4 = B_ * T_ * D4;
    bidaf_k3<<<(total4 + 255) / 256, 256>>>(h, out);
}

// round 12
// speedup vs baseline: 1.2337x; 1.2337x over previous
#include <cuda_runtime.h>

#define B_ 64
#define T_ 800
#define J_ 50
#define D_ 200

constexpr int TPB  = 256;
constexpr int TBLK = 64;         // t-rows per block
constexpr int NBLK = 13;         // ceil(800/64); last block has 32 valid rows
constexpr int UP   = 204;        // u_s pitch (floats)
constexpr int UP4  = 51;
constexpr int AP   = 68;         // a_s pitch (floats)
constexpr int JP   = 64;         // padded J
constexpr int NKS  = 25;         // k-steps (200/8) for s-GEMM

// scratch (no cudaMalloc allowed)
__device__ float2 g_cm[B_ * NBLK];
__device__ float  g_part[B_ * NBLK * D_];
__device__ __align__(16) float g_q2c[B_ * D_];

__device__ __forceinline__ float warpSum(float v) {
    #pragma unroll
    for (int o = 16; o > 0; o >>= 1) v += __shfl_xor_sync(0xffffffffu, v, o);
    return v;
}
__device__ __forceinline__ float warpMax(float v) {
    #pragma unroll
    for (int o = 16; o > 0; o >>= 1) v = fmaxf(v, __shfl_xor_sync(0xffffffffu, v, o));
    return v;
}
__device__ __forceinline__ void mma8(float d[4], const unsigned a[4], const unsigned b[2]) {
    asm("mma.sync.aligned.m16n8k8.row.col.f32.tf32.tf32.f32 "
        "{%0,%1,%2,%3}, {%4,%5,%6,%7}, {%8,%9}, {%0,%1,%2,%3};"
        : "+f"(d[0]), "+f"(d[1]), "+f"(d[2]), "+f"(d[3])
        : "r"(a[0]), "r"(a[1]), "r"(a[2]), "r"(a[3]), "r"(b[0]), "r"(b[1]));
}
__device__ __forceinline__ void split2(float x, unsigned& hi, unsigned& lo) {
    unsigned hh = __float_as_uint(x) & 0xffffe000u;
    hi = hh;
    lo = __float_as_uint(x - __uint_as_float(hh));
}

// c2q chunk: NTN n-tiles starting at ntBeg (d columns dbase + 8*nt)
template<int NTN>
__device__ __forceinline__ void c2q_chunk(
    int ntBeg, int dbase, const float* a_s, const float* u_s,
    int strip, int g, int tg,
    const float* hp0, const float* hp1, bool v0, bool v1,
    float* o0, float* o1)
{
    float dacc[NTN][4];
    #pragma unroll
    for (int q = 0; q < NTN; q++) {
        dacc[q][0] = 0.f; dacc[q][1] = 0.f; dacc[q][2] = 0.f; dacc[q][3] = 0.f;
    }
    const float* aR0 = a_s + (strip * 16 + g) * AP;
    const float* aR1 = aR0 + 8 * AP;
    #pragma unroll
    for (int ks = 0; ks < 8; ks++) {
        const int k0 = ks * 8 + tg;
        unsigned ah[4], al[4];
        split2(aR0[k0],     ah[0], al[0]);
        split2(aR1[k0],     ah[1], al[1]);
        split2(aR0[k0 + 4], ah[2], al[2]);
        split2(aR1[k0 + 4], ah[3], al[3]);
        const float* uk0 = u_s + k0 * UP + g;      // B[k=j][n=d]
        const float* uk1 = uk0 + 4 * UP;
        #pragma unroll
        for (int q = 0; q < NTN; q++) {
            const int nb = dbase + (ntBeg + q) * 8;
            unsigned bh[2], bl[2];
            split2(uk0[nb], bh[0], bl[0]);
            split2(uk1[nb], bh[1], bl[1]);
            mma8(dacc[q], ah, bh);
            mma8(dacc[q], al, bh);
            mma8(dacc[q], ah, bl);
        }
    }
    #pragma unroll
    for (int q = 0; q < NTN; q++) {
        const int cc = dbase + (ntBeg + q) * 8 + 2 * tg;
        if (v0) {
            float2 hv = *(const float2*)&hp0[cc];
            float2 c2 = make_float2(dacc[q][0], dacc[q][1]);
            __stcs((float2*)(o0 + cc), hv);
            __stcs((float2*)(o0 + 200 + cc), c2);
            __stcs((float2*)(o0 + 400 + cc), make_float2(hv.x * c2.x, hv.y * c2.y));
        }
        if (v1) {
            float2 hv = *(const float2*)&hp1[cc];
            float2 c2 = make_float2(dacc[q][2], dacc[q][3]);
            __stcs((float2*)(o1 + cc), hv);
            __stcs((float2*)(o1 + 200 + cc), c2);
            __stcs((float2*)(o1 + 400 + cc), make_float2(hv.x * c2.x, hv.y * c2.y));
        }
    }
}

// =====================================================================
// K1 (3xTF32 tensor-core)
// =====================================================================
__global__ __launch_bounds__(TPB, 3) void bidaf_k1(
    const float* __restrict__ h, const float* __restrict__ u,
    const float* __restrict__ w_h, const float* __restrict__ b_h,
    const float* __restrict__ w_u, const float* __restrict__ b_u,
    const float* __restrict__ w_hu, const float* __restrict__ b_hu,
    float* __restrict__ out)
{
    extern __shared__ float sm[];
    float* u_s   = sm;                       // 64*204
    float* a_s   = sm + JP * UP;             // 64*68
    float* su_s  = a_s + JP * AP;            // 64
    float* sh_s  = su_s + JP;                // 64
    float* whu_s = sh_s + JP;                // 200
    float* m_s   = whu_s + D_;               // 64
    float* es_s  = m_s + JP;                 // 64

    const int b = blockIdx.y, c = blockIdx.x, t0 = c * TBLK;
    const int tid = threadIdx.x, warp = tid >> 5, lane = tid & 31;
    const int g = lane >> 2, tg = lane & 3;
    const int strip = warp & 3;     // m16 strip
    const int nh = warp >> 2;       // n-half

    const float4* u4g = (const float4*)u;
    const float4* h4g = (const float4*)h;
    float4* us4 = (float4*)u_s;
    const float* hb = h + (long)b * T_ * D_;

    // ---- u tile (rows/cols zero-padded) + whu copy ----
    for (int idx = tid; idx < JP * UP4; idx += TPB) {
        int j = idx / UP4, k = idx - j * UP4;
        float4 v = make_float4(0.f, 0.f, 0.f, 0.f);
        if (j < J_ && k < 50) v = u4g[(b * J_ + j) * 50 + k];
        us4[j * UP4 + k] = v;
    }
    if (tid < 50) ((float4*)whu_s)[tid] = ((const float4*)w_hu)[tid];
    const float bias = b_h[0] + b_u[0] + b_hu[0];
    __syncthreads();

    // ---- su_s[j] (pad rows -> -1e30) ----
    const float4* wu4 = (const float4*)w_u;
    for (int j = warp; j < JP; j += 8) {
        if (j < J_) {
            float4 a1 = us4[j * UP4 + lane], w1 = wu4[lane];
            float acc = a1.x * w1.x + a1.y * w1.y + a1.z * w1.z + a1.w * w1.w;
            if (lane < 18) {
                float4 a2 = us4[j * UP4 + 32 + lane], w2 = wu4[32 + lane];
                acc += a2.x * w2.x + a2.y * w2.y + a2.z * w2.z + a2.w * w2.w;
            }
            acc = warpSum(acc);
            if (lane == 0) su_s[j] = acc + bias;
        } else if (lane == 0) su_s[j] = -1e30f;
    }

    // ---- sh: warp w rows 8w..8w+7 (clamped for tail block) ----
    {
        const float4* wh4 = (const float4*)w_h;
        float4 w1 = wh4[lane];
        float4 w2 = make_float4(0.f, 0.f, 0.f, 0.f);
        if (lane < 18) w2 = wh4[32 + lane];
        #pragma unroll
        for (int rr = 0; rr < 8; rr++) {
            int t = t0 + warp * 8 + rr; if (t > T_ - 1) t = T_ - 1;
            long rb = (long)(b * T_ + t) * 50;
            float4 a1 = h4g[rb + lane];
            float p = a1.x * w1.x + a1.y * w1.y + a1.z * w1.z + a1.w * w1.w;
            if (lane < 18) {
                float4 a2 = h4g[rb + 32 + lane];
                p += a2.x * w2.x + a2.y * w2.y + a2.z * w2.z + a2.w * w2.w;
            }
            p = warpSum(p);
            if (lane == 0) sh_s[warp * 8 + rr] = p;
        }
    }
    __syncthreads();

    // ---- s-GEMM: A = (h*whu) from global, B = u_s; warp=(strip,nh) ----
    {
        int tA0 = t0 + strip * 16 + g;     if (tA0 > T_ - 1) tA0 = T_ - 1;
        int tA1 = t0 + strip * 16 + g + 8; if (tA1 > T_ - 1) tA1 = T_ - 1;
        const float* hr0 = hb + (long)tA0 * D_;
        const float* hr1 = hb + (long)tA1 * D_;

        float acc[4][4];
        #pragma unroll
        for (int nt = 0; nt < 4; nt++) {
            acc[nt][0] = 0.f; acc[nt][1] = 0.f; acc[nt][2] = 0.f; acc[nt][3] = 0.f;
        }
        #pragma unroll 2
        for (int ks = 0; ks < NKS; ks++) {
            const int c0 = ks * 8 + tg, c1 = c0 + 4;
            const float w0 = whu_s[c0], w1 = whu_s[c1];
            unsigned ah[4], al[4];
            split2(hr0[c0] * w0, ah[0], al[0]);
            split2(hr1[c0] * w0, ah[1], al[1]);
            split2(hr0[c1] * w1, ah[2], al[2]);
            split2(hr1[c1] * w1, ah[3], al[3]);
            #pragma unroll
            for (int nt = 0; nt < 4; nt++) {
                const float* ur = u_s + (nh * 32 + nt * 8 + g) * UP;  // B[k=d][n=j]
                unsigned bh[2], bl[2];
                split2(ur[c0], bh[0], bl[0]);
                split2(ur[c1], bh[1], bl[1]);
                mma8(acc[nt], ah, bh);
                mma8(acc[nt], al, bh);
                mma8(acc[nt], ah, bl);
            }
        }
        const float sh0 = sh_s[strip * 16 + g], sh1 = sh_s[strip * 16 + g + 8];
        float* sr0 = a_s + (strip * 16 + g) * AP;
        float* sr1 = sr0 + 8 * AP;
        #pragma unroll
        for (int nt = 0; nt < 4; nt++) {
            const int cc = nh * 32 + nt * 8 + 2 * tg;
            float2 su2 = *(const float2*)&su_s[cc];
            *(float2*)&sr0[cc] = make_float2(acc[nt][0] + sh0 + su2.x,
                                             acc[nt][1] + sh0 + su2.y);
            *(float2*)&sr1[cc] = make_float2(acc[nt][2] + sh1 + su2.x,
                                             acc[nt][3] + sh1 + su2.y);
        }
    }
    __syncthreads();

    // ---- softmax: 4 threads per row, in place ----
    {
        const int row = tid >> 2, q = tid & 3;
        float4* ar = (float4*)&a_s[row * AP + q * 16];
        float4 v0 = ar[0], v1 = ar[1], v2 = ar[2], v3 = ar[3];
        float mx = fmaxf(fmaxf(fmaxf(v0.x, v0.y), fmaxf(v0.z, v0.w)),
                   fmaxf(fmaxf(fmaxf(v1.x, v1.y), fmaxf(v1.z, v1.w)),
                   fmaxf(fmaxf(fmaxf(v2.x, v2.y), fmaxf(v2.z, v2.w)),
                         fmaxf(fmaxf(v3.x, v3.y), fmaxf(v3.z, v3.w)))));
        mx = fmaxf(mx, __shfl_xor_sync(0xffffffffu, mx, 1));
        mx = fmaxf(mx, __shfl_xor_sync(0xffffffffu, mx, 2));
        v0.x = __expf(v0.x - mx); v0.y = __expf(v0.y - mx);
        v0.z = __expf(v0.z - mx); v0.w = __expf(v0.w - mx);
        v1.x = __expf(v1.x - mx); v1.y = __expf(v1.y - mx);
        v1.z = __expf(v1.z - mx); v1.w = __expf(v1.w - mx);
        v2.x = __expf(v2.x - mx); v2.y = __expf(v2.y - mx);
        v2.z = __expf(v2.z - mx); v2.w = __expf(v2.w - mx);
        v3.x = __expf(v3.x - mx); v3.y = __expf(v3.y - mx);
        v3.z = __expf(v3.z - mx); v3.w = __expf(v3.w - mx);
        float s = (v0.x + v0.y + v0.z + v0.w) + (v1.x + v1.y + v1.z + v1.w)
                + (v2.x + v2.y + v2.z + v2.w) + (v3.x + v3.y + v3.z + v3.w);
        s += __shfl_xor_sync(0xffffffffu, s, 1);
        s += __shfl_xor_sync(0xffffffffu, s, 2);
        const float inv = 1.f / s;
        v0.x *= inv; v0.y *= inv; v0.z *= inv; v0.w *= inv;
        v1.x *= inv; v1.y *= inv; v1.z *= inv; v1.w *= inv;
        v2.x *= inv; v2.y *= inv; v2.z *= inv; v2.w *= inv;
        v3.x *= inv; v3.y *= inv; v3.z *= inv; v3.w *= inv;
        ar[0] = v0; ar[1] = v1; ar[2] = v2; ar[3] = v3;
        if (q == 0) m_s[row] = (t0 + row < T_) ? mx : -3.0e38f;
    }
    __syncthreads();

    // ---- warp 0: chunk max/expsum over 64 rows ----
    if (warp == 0) {
        float m0 = m_s[lane], m1 = m_s[lane + 32];
        float mc = warpMax(fmaxf(m0, m1));
        float e0 = __expf(m0 - mc), e1 = __expf(m1 - mc);
        float sc = warpSum(e0 + e1);
        es_s[lane] = e0; es_s[lane + 32] = e1;
        if (lane == 0) g_cm[b * NBLK + c] = make_float2(mc, sc);
    }

    // ---- c2q GEMM + fused epilogue ----
    {
        const int dbase = nh * 104;      // half0: 13 tiles (d 0..103), half1: 12 (104..199)
        const int tr0 = t0 + strip * 16 + g, tr1 = tr0 + 8;
        const bool v0 = tr0 < T_, v1 = tr1 < T_;
        const float* hp0 = hb + (long)(v0 ? tr0 : 0) * D_;
        const float* hp1 = hb + (long)(v1 ? tr1 : 0) * D_;
        float* o0 = out + (long)(b * T_ + (v0 ? tr0 : 0)) * (4 * D_);
        float* o1 = out + (long)(b * T_ + (v1 ? tr1 : 0)) * (4 * D_);
        if (nh == 0) {
            c2q_chunk<7>(0, dbase, a_s, u_s, strip, g, tg, hp0, hp1, v0, v1, o0, o1);
            c2q_chunk<6>(7, dbase, a_s, u_s, strip, g, tg, hp0, hp1, v0, v1, o0, o1);
        } else {
            c2q_chunk<7>(0, dbase, a_s, u_s, strip, g, tg, hp0, hp1, v0, v1, o0, o1);
            c2q_chunk<5>(7, dbase, a_s, u_s, strip, g, tg, hp0, hp1, v0, v1, o0, o1);
        }
    }

    // ---- chunk-local q2c partial ----
    __syncthreads();
    if (tid < D_) {
        const int RV = (T_ - t0 < TBLK) ? (T_ - t0) : TBLK;
        const float* hp = hb + (long)t0 * D_ + tid;
        float a0 = 0.f, a1 = 0.f, a2 = 0.f, a3 = 0.f;
        for (int r = 0; r < RV; r += 4) {
            a0 += es_s[r]     * hp[r * D_];
            a1 += es_s[r + 1] * hp[(r + 1) * D_];
            a2 += es_s[r + 2] * hp[(r + 2) * D_];
            a3 += es_s[r + 3] * hp[(r + 3) * D_];
        }
        g_part[(b * NBLK + c) * D_ + tid] = (a0 + a1) + (a2 + a3);
    }
}

// =====================================================================
// K2: per-batch combine -> g_q2c
// =====================================================================
__global__ __launch_bounds__(256) void bidaf_k2()
{
    __shared__ float ws[32];
    __shared__ float Ss;
    const int b = blockIdx.x, tid = threadIdx.x;
    if (tid < 32) {
        float2 cm = (tid < NBLK) ? g_cm[b * NBLK + tid] : make_float2(-3.0e38f, 0.f);
        float M = warpMax(cm.x);
        float e = (tid < NBLK) ? __expf(cm.x - M) : 0.f;
        float S = warpSum(e * cm.y);
        ws[tid] = e;
        if (tid == 0) Ss = S;
    }
    __syncthreads();
    if (tid < D_) {
        float acc = 0.f;
        #pragma unroll
        for (int c2 = 0; c2 < NBLK; c2++)
            acc += ws[c2] * g_part[(b * NBLK + c2) * D_ + tid];
        g_q2c[b * D_ + tid] = acc / Ss;
    }
}

// =====================================================================
// K3: out[b,t,600:800] = h * q2c
// =====================================================================
__global__ __launch_bounds__(256) void bidaf_k3(const float* __restrict__ h,
                                                float* __restrict__ out)
{
    long idx = (long)blockIdx.x * 256 + threadIdx.x;   // float4 index
    if (idx >= (long)B_ * T_ * 50) return;
    int d4 = (int)(idx % 50);
    long bt = idx / 50;
    int b = (int)(bt / T_);
    float4 hv = __ldg(((const float4*)h) + idx);
    float4 q  = __ldg(((const float4*)g_q2c) + b * 50 + d4);
    __stcs(((float4*)out) + bt * 200 + 150 + d4,
           make_float4(hv.x * q.x, hv.y * q.y, hv.z * q.z, hv.w * q.w));
}

// =====================================================================
extern "C" void kernel_launch(void* const* d_in, const int* in_sizes, int n_in,
                              void* d_out, int out_size)
{
    const float* h    = (const float*)d_in[0];
    const float* u    = (const float*)d_in[1];
    const float* w_h  = (const float*)d_in[2];
    const float* b_h  = (const float*)d_in[3];
    const float* w_u  = (const float*)d_in[4];
    const float* b_u  = (const float*)d_in[5];
    const float* w_hu = (const float*)d_in[6];
    const float* b_hu = (const float*)d_in[7];
    float* out = (float*)d_out;

    constexpr int SMEM1 = (JP * UP + JP * AP + JP + JP + D_ + JP + JP) * 4; // 71456
    cudaFuncSetAttribute(bidaf_k1, cudaFuncAttributeMaxDynamicSharedMemorySize, SMEM1);

    bidaf_k1<<<dim3(NBLK, B_), TPB, SMEM1>>>(h, u, w_h, b_h, w_u, b_u, w_hu, b_hu, out);
    bidaf_k2<<<B_, 256>>>();
    int total4 = B_ * T_ * 50;
    bidaf_k3<<<(total4 + 255) / 256, 256>>>(h, out);
}

// round 13
// speedup vs baseline: 1.2455x; 1.0096x over previous
#include <cuda_runtime.h>

#define B_ 64
#define T_ 800
#define J_ 50
#define D_ 200

constexpr int TPB  = 256;
constexpr int TBLK = 64;         // t-rows per block
constexpr int NBLK = 13;         // ceil(800/64)
constexpr int UP   = 204;        // u_s pitch (floats)
constexpr int UP4  = 51;
constexpr int AP   = 68;         // a_s pitch (floats)
constexpr int JP   = 64;         // padded J
constexpr int STP  = 36;         // staging pitch (floats): A-frag reads conflict-free

// scratch (no cudaMalloc allowed)
__device__ float2 g_cm[B_ * NBLK];
__device__ float  g_part[B_ * NBLK * D_];
__device__ __align__(16) float g_q2c[B_ * D_];

__device__ __forceinline__ float warpSum(float v) {
    #pragma unroll
    for (int o = 16; o > 0; o >>= 1) v += __shfl_xor_sync(0xffffffffu, v, o);
    return v;
}
__device__ __forceinline__ float warpMax(float v) {
    #pragma unroll
    for (int o = 16; o > 0; o >>= 1) v = fmaxf(v, __shfl_xor_sync(0xffffffffu, v, o));
    return v;
}
__device__ __forceinline__ void mma8(float d[4], const unsigned a[4], const unsigned b[2]) {
    asm("mma.sync.aligned.m16n8k8.row.col.f32.tf32.tf32.f32 "
        "{%0,%1,%2,%3}, {%4,%5,%6,%7}, {%8,%9}, {%0,%1,%2,%3};"
        : "+f"(d[0]), "+f"(d[1]), "+f"(d[2]), "+f"(d[3])
        : "r"(a[0]), "r"(a[1]), "r"(a[2]), "r"(a[3]), "r"(b[0]), "r"(b[1]));
}
__device__ __forceinline__ void split2(float x, unsigned& hi, unsigned& lo) {
    unsigned hh = __float_as_uint(x) & 0xffffe000u;
    hi = hh;
    lo = __float_as_uint(x - __uint_as_float(hh));
}

// c2q chunk: NTN n-tiles starting at ntBeg (d columns dbase + 8*nt)
template<int NTN>
__device__ __forceinline__ void c2q_chunk(
    int ntBeg, int dbase, const float* a_s, const float* u_s,
    int strip, int g, int tg,
    const float* hp0, const float* hp1, bool v0, bool v1,
    float* o0, float* o1)
{
    float dacc[NTN][4];
    #pragma unroll
    for (int q = 0; q < NTN; q++) {
        dacc[q][0] = 0.f; dacc[q][1] = 0.f; dacc[q][2] = 0.f; dacc[q][3] = 0.f;
    }
    const float* aR0 = a_s + (strip * 16 + g) * AP;
    const float* aR1 = aR0 + 8 * AP;
    #pragma unroll
    for (int ks = 0; ks < 8; ks++) {
        const int k0 = ks * 8 + tg;
        unsigned ah[4], al[4];
        split2(aR0[k0],     ah[0], al[0]);
        split2(aR1[k0],     ah[1], al[1]);
        split2(aR0[k0 + 4], ah[2], al[2]);
        split2(aR1[k0 + 4], ah[3], al[3]);
        const float* uk0 = u_s + k0 * UP + g;      // B[k=j][n=d]
        const float* uk1 = uk0 + 4 * UP;
        #pragma unroll
        for (int q = 0; q < NTN; q++) {
            const int nb = dbase + (ntBeg + q) * 8;
            unsigned bh[2], bl[2];
            split2(uk0[nb], bh[0], bl[0]);
            split2(uk1[nb], bh[1], bl[1]);
            mma8(dacc[q], ah, bh);
            mma8(dacc[q], al, bh);
            mma8(dacc[q], ah, bl);
        }
    }
    #pragma unroll
    for (int q = 0; q < NTN; q++) {
        const int cc = dbase + (ntBeg + q) * 8 + 2 * tg;
        if (v0) {
            float2 hv = *(const float2*)&hp0[cc];
            float2 c2 = make_float2(dacc[q][0], dacc[q][1]);
            __stcs((float2*)(o0 + cc), hv);
            __stcs((float2*)(o0 + 200 + cc), c2);
            __stcs((float2*)(o0 + 400 + cc), make_float2(hv.x * c2.x, hv.y * c2.y));
        }
        if (v1) {
            float2 hv = *(const float2*)&hp1[cc];
            float2 c2 = make_float2(dacc[q][2], dacc[q][3]);
            __stcs((float2*)(o1 + cc), hv);
            __stcs((float2*)(o1 + 200 + cc), c2);
            __stcs((float2*)(o1 + 400 + cc), make_float2(hv.x * c2.x, hv.y * c2.y));
        }
    }
}

// =====================================================================
// K1 (3xTF32 tensor-core, smem-staged A path)
// =====================================================================
__global__ __launch_bounds__(TPB, 3) void bidaf_k1(
    const float* __restrict__ h, const float* __restrict__ u,
    const float* __restrict__ w_h, const float* __restrict__ b_h,
    const float* __restrict__ w_u, const float* __restrict__ b_u,
    const float* __restrict__ w_hu, const float* __restrict__ b_hu,
    float* __restrict__ out)
{
    extern __shared__ float sm[];
    float* u_s   = sm;                       // 64*204
    float* a_s   = sm + JP * UP;             // 64*68  (staging tile overlays, then s/a tile)
    float* su_s  = a_s + JP * AP;            // 64
    float* sh_s  = su_s + JP;                // 64
    float* whu_s = sh_s + JP;                // 200
    float* whs_s = whu_s + D_;               // 200
    float* m_s   = whs_s + D_;               // 64
    float* es_s  = m_s + JP;                 // 64

    const int b = blockIdx.y, c = blockIdx.x, t0 = c * TBLK;
    const int tid = threadIdx.x, warp = tid >> 5, lane = tid & 31;
    const int g = lane >> 2, tg = lane & 3;
    const int strip = warp & 3;     // m16 strip
    const int nh = warp >> 2;       // n-half

    const float4* u4g = (const float4*)u;
    const float4* h4g = (const float4*)h;
    float4* us4 = (float4*)u_s;
    const float* hb = h + (long)b * T_ * D_;

    // ---- u tile (rows/cols zero-padded) + weight copies ----
    for (int idx = tid; idx < JP * UP4; idx += TPB) {
        int j = idx / UP4, k = idx - j * UP4;
        float4 v = make_float4(0.f, 0.f, 0.f, 0.f);
        if (j < J_ && k < 50) v = u4g[(b * J_ + j) * 50 + k];
        us4[j * UP4 + k] = v;
    }
    if (tid < 50) ((float4*)whu_s)[tid] = ((const float4*)w_hu)[tid];
    else if (tid >= 64 && tid < 114) ((float4*)whs_s)[tid - 64] = ((const float4*)w_h)[tid - 64];
    const float bias = b_h[0] + b_u[0] + b_hu[0];
    __syncthreads();

    // ---- su_s[j] (pad rows -> -1e30) ----
    const float4* wu4 = (const float4*)w_u;
    for (int j = warp; j < JP; j += 8) {
        if (j < J_) {
            float4 a1 = us4[j * UP4 + lane], w1 = wu4[lane];
            float acc = a1.x * w1.x + a1.y * w1.y + a1.z * w1.z + a1.w * w1.w;
            if (lane < 18) {
                float4 a2 = us4[j * UP4 + 32 + lane], w2 = wu4[32 + lane];
                acc += a2.x * w2.x + a2.y * w2.y + a2.z * w2.z + a2.w * w2.w;
            }
            acc = warpSum(acc);
            if (lane == 0) su_s[j] = acc + bias;
        } else if (lane == 0) su_s[j] = -1e30f;
    }

    // ---- s-GEMM with staged A (hw) through a_s region; sh fused in ----
    {
        float accS[4][4];
        #pragma unroll
        for (int nt = 0; nt < 4; nt++) {
            accS[nt][0] = 0.f; accS[nt][1] = 0.f; accS[nt][2] = 0.f; accS[nt][3] = 0.f;
        }
        float shp0 = 0.f, shp1 = 0.f;
        const int srow = tid >> 3, sc = tid & 7;      // staging row (r=0) / f4 col
        float* stage = a_s;                           // pitch STP=36
        const float4* whu4s = (const float4*)whu_s;
        const float4* wh4s  = (const float4*)whs_s;
        const float* st0 = stage + (strip * 16 + g) * STP;
        const float* st1 = st0 + 8 * STP;

        #pragma unroll
        for (int rd = 0; rd < 7; rd++) {
            const int dbase = rd * 32;
            const int nf4 = (rd < 6) ? 8 : 2;
            __syncthreads();                           // prev round consumed
            if (sc < nf4) {
                const int cf4 = (dbase >> 2) + sc;
                float4 wv  = whu4s[cf4];
                float4 whv = wh4s[cf4];
                {
                    int t = t0 + srow; if (t > T_ - 1) t = T_ - 1;
                    float4 hv = h4g[(long)(b * T_ + t) * 50 + cf4];
                    *(float4*)&stage[srow * STP + sc * 4] =
                        make_float4(hv.x * wv.x, hv.y * wv.y, hv.z * wv.z, hv.w * wv.w);
                    shp0 += hv.x * whv.x + hv.y * whv.y + hv.z * whv.z + hv.w * whv.w;
                }
                {
                    int t = t0 + srow + 32; if (t > T_ - 1) t = T_ - 1;
                    float4 hv = h4g[(long)(b * T_ + t) * 50 + cf4];
                    *(float4*)&stage[(srow + 32) * STP + sc * 4] =
                        make_float4(hv.x * wv.x, hv.y * wv.y, hv.z * wv.z, hv.w * wv.w);
                    shp1 += hv.x * whv.x + hv.y * whv.y + hv.z * whv.z + hv.w * whv.w;
                }
            }
            __syncthreads();                           // stage ready
            const int nks = (rd < 6) ? 4 : 1;
            for (int ksl = 0; ksl < nks; ksl++) {
                const int c0 = ksl * 8 + tg, c1 = c0 + 4;
                const int kd0 = dbase + c0, kd1 = dbase + c1;
                unsigned ah[4], al[4];
                split2(st0[c0], ah[0], al[0]);
                split2(st1[c0], ah[1], al[1]);
                split2(st0[c1], ah[2], al[2]);
                split2(st1[c1], ah[3], al[3]);
                #pragma unroll
                for (int nt = 0; nt < 4; nt++) {
                    const float* ur = u_s + (nh * 32 + nt * 8 + g) * UP;
                    unsigned bh[2], bl[2];
                    split2(ur[kd0], bh[0], bl[0]);
                    split2(ur[kd1], bh[1], bl[1]);
                    mma8(accS[nt], ah, bh);
                    mma8(accS[nt], al, bh);
                    mma8(accS[nt], ah, bl);
                }
            }
        }
        // finalize sh (8-lane groups are consecutive lanes)
        shp0 += __shfl_down_sync(0xffffffffu, shp0, 4);
        shp0 += __shfl_down_sync(0xffffffffu, shp0, 2);
        shp0 += __shfl_down_sync(0xffffffffu, shp0, 1);
        shp1 += __shfl_down_sync(0xffffffffu, shp1, 4);
        shp1 += __shfl_down_sync(0xffffffffu, shp1, 2);
        shp1 += __shfl_down_sync(0xffffffffu, shp1, 1);
        if ((tid & 7) == 0) {
            sh_s[tid >> 3] = shp0;
            sh_s[32 + (tid >> 3)] = shp1;
        }
        __syncthreads();                               // stage dead, sh_s ready

        const float sh0 = sh_s[strip * 16 + g], sh1 = sh_s[strip * 16 + g + 8];
        float* sr0 = a_s + (strip * 16 + g) * AP;
        float* sr1 = sr0 + 8 * AP;
        #pragma unroll
        for (int nt = 0; nt < 4; nt++) {
            const int cc = nh * 32 + nt * 8 + 2 * tg;
            float2 su2 = *(const float2*)&su_s[cc];
            *(float2*)&sr0[cc] = make_float2(accS[nt][0] + sh0 + su2.x,
                                             accS[nt][1] + sh0 + su2.y);
            *(float2*)&sr1[cc] = make_float2(accS[nt][2] + sh1 + su2.x,
                                             accS[nt][3] + sh1 + su2.y);
        }
    }
    __syncthreads();

    // ---- softmax: 4 threads per row, in place ----
    {
        const int row = tid >> 2, q = tid & 3;
        float4* ar = (float4*)&a_s[row * AP + q * 16];
        float4 v0 = ar[0], v1 = ar[1], v2 = ar[2], v3 = ar[3];
        float mx = fmaxf(fmaxf(fmaxf(v0.x, v0.y), fmaxf(v0.z, v0.w)),
                   fmaxf(fmaxf(fmaxf(v1.x, v1.y), fmaxf(v1.z, v1.w)),
                   fmaxf(fmaxf(fmaxf(v2.x, v2.y), fmaxf(v2.z, v2.w)),
                         fmaxf(fmaxf(v3.x, v3.y), fmaxf(v3.z, v3.w)))));
        mx = fmaxf(mx, __shfl_xor_sync(0xffffffffu, mx, 1));
        mx = fmaxf(mx, __shfl_xor_sync(0xffffffffu, mx, 2));
        v0.x = __expf(v0.x - mx); v0.y = __expf(v0.y - mx);
        v0.z = __expf(v0.z - mx); v0.w = __expf(v0.w - mx);
        v1.x = __expf(v1.x - mx); v1.y = __expf(v1.y - mx);
        v1.z = __expf(v1.z - mx); v1.w = __expf(v1.w - mx);
        v2.x = __expf(v2.x - mx); v2.y = __expf(v2.y - mx);
        v2.z = __expf(v2.z - mx); v2.w = __expf(v2.w - mx);
        v3.x = __expf(v3.x - mx); v3.y = __expf(v3.y - mx);
        v3.z = __expf(v3.z - mx); v3.w = __expf(v3.w - mx);
        float s = (v0.x + v0.y + v0.z + v0.w) + (v1.x + v1.y + v1.z + v1.w)
                + (v2.x + v2.y + v2.z + v2.w) + (v3.x + v3.y + v3.z + v3.w);
        s += __shfl_xor_sync(0xffffffffu, s, 1);
        s += __shfl_xor_sync(0xffffffffu, s, 2);
        const float inv = 1.f / s;
        v0.x *= inv; v0.y *= inv; v0.z *= inv; v0.w *= inv;
        v1.x *= inv; v1.y *= inv; v1.z *= inv; v1.w *= inv;
        v2.x *= inv; v2.y *= inv; v2.z *= inv; v2.w *= inv;
        v3.x *= inv; v3.y *= inv; v3.z *= inv; v3.w *= inv;
        ar[0] = v0; ar[1] = v1; ar[2] = v2; ar[3] = v3;
        if (q == 0) m_s[row] = (t0 + row < T_) ? mx : -3.0e38f;
    }
    __syncthreads();

    // ---- warp 0: chunk max/expsum over 64 rows ----
    if (warp == 0) {
        float m0 = m_s[lane], m1 = m_s[lane + 32];
        float mc = warpMax(fmaxf(m0, m1));
        float e0 = __expf(m0 - mc), e1 = __expf(m1 - mc);
        float sc2 = warpSum(e0 + e1);
        es_s[lane] = e0; es_s[lane + 32] = e1;
        if (lane == 0) g_cm[b * NBLK + c] = make_float2(mc, sc2);
    }

    // ---- c2q GEMM + fused epilogue ----
    {
        const int dbase = nh * 104;      // half0: 13 tiles, half1: 12 tiles
        const int tr0 = t0 + strip * 16 + g, tr1 = tr0 + 8;
        const bool v0 = tr0 < T_, v1 = tr1 < T_;
        const float* hp0 = hb + (long)(v0 ? tr0 : 0) * D_;
        const float* hp1 = hb + (long)(v1 ? tr1 : 0) * D_;
        float* o0 = out + (long)(b * T_ + (v0 ? tr0 : 0)) * (4 * D_);
        float* o1 = out + (long)(b * T_ + (v1 ? tr1 : 0)) * (4 * D_);
        if (nh == 0) {
            c2q_chunk<7>(0, dbase, a_s, u_s, strip, g, tg, hp0, hp1, v0, v1, o0, o1);
            c2q_chunk<6>(7, dbase, a_s, u_s, strip, g, tg, hp0, hp1, v0, v1, o0, o1);
        } else {
            c2q_chunk<7>(0, dbase, a_s, u_s, strip, g, tg, hp0, hp1, v0, v1, o0, o1);
            c2q_chunk<5>(7, dbase, a_s, u_s, strip, g, tg, hp0, hp1, v0, v1, o0, o1);
        }
    }

    // ---- chunk-local q2c partial ----
    __syncthreads();
    if (tid < D_) {
        const int RV = (T_ - t0 < TBLK) ? (T_ - t0) : TBLK;
        const float* hp = hb + (long)t0 * D_ + tid;
        float a0 = 0.f, a1 = 0.f, a2 = 0.f, a3 = 0.f;
        for (int r = 0; r < RV; r += 4) {
            a0 += es_s[r]     * hp[r * D_];
            a1 += es_s[r + 1] * hp[(r + 1) * D_];
            a2 += es_s[r + 2] * hp[(r + 2) * D_];
            a3 += es_s[r + 3] * hp[(r + 3) * D_];
        }
        g_part[(b * NBLK + c) * D_ + tid] = (a0 + a1) + (a2 + a3);
    }
}

// =====================================================================
// K2: per-batch combine -> g_q2c
// =====================================================================
__global__ __launch_bounds__(256) void bidaf_k2()
{
    __shared__ float ws[32];
    __shared__ float Ss;
    const int b = blockIdx.x, tid = threadIdx.x;
    if (tid < 32) {
        float2 cm = (tid < NBLK) ? g_cm[b * NBLK + tid] : make_float2(-3.0e38f, 0.f);
        float M = warpMax(cm.x);
        float e = (tid < NBLK) ? __expf(cm.x - M) : 0.f;
        float S = warpSum(e * cm.y);
        ws[tid] = e;
        if (tid == 0) Ss = S;
    }
    __syncthreads();
    if (tid < D_) {
        float acc = 0.f;
        #pragma unroll
        for (int c2 = 0; c2 < NBLK; c2++)
            acc += ws[c2] * g_part[(b * NBLK + c2) * D_ + tid];
        g_q2c[b * D_ + tid] = acc / Ss;
    }
}

// =====================================================================
// K3: out[b,t,600:800] = h * q2c
// =====================================================================
__global__ __launch_bounds__(256) void bidaf_k3(const float* __restrict__ h,
                                                float* __restrict__ out)
{
    long idx = (long)blockIdx.x * 256 + threadIdx.x;   // float4 index
    if (idx >= (long)B_ * T_ * 50) return;
    int d4 = (int)(idx % 50);
    long bt = idx / 50;
    int b = (int)(bt / T_);
    float4 hv = __ldg(((const float4*)h) + idx);
    float4 q  = __ldg(((const float4*)g_q2c) + b * 50 + d4);
    __stcs(((float4*)out) + bt * 200 + 150 + d4,
           make_float4(hv.x * q.x, hv.y * q.y, hv.z * q.z, hv.w * q.w));
}

// =====================================================================
extern "C" void kernel_launch(void* const* d_in, const int* in_sizes, int n_in,
                              void* d_out, int out_size)
{
    const float* h    = (const float*)d_in[0];
    const float* u    = (const float*)d_in[1];
    const float* w_h  = (const float*)d_in[2];
    const float* b_h  = (const float*)d_in[3];
    const float* w_u  = (const float*)d_in[4];
    const float* b_u  = (const float*)d_in[5];
    const float* w_hu = (const float*)d_in[6];
    const float* b_hu = (const float*)d_in[7];
    float* out = (float*)d_out;

    // u_s + a_s + su + sh + whu + whs + m + es
    constexpr int SMEM1 = (JP * UP + JP * AP + JP + JP + D_ + D_ + JP + JP) * 4; // 72256
    cudaFuncSetAttribute(bidaf_k1, cudaFuncAttributeMaxDynamicSharedMemorySize, SMEM1);

    bidaf_k1<<<dim3(NBLK, B_), TPB, SMEM1>>>(h, u, w_h, b_h, w_u, b_u, w_hu, b_hu, out);
    bidaf_k2<<<B_, 256>>>();
    int total4 = B_ * T_ * 50;
    bidaf_k3<<<(total4 + 255) / 256, 256>>>(h, out);
}

// round 14
// speedup vs baseline: 1.3492x; 1.0833x over previous
#include <cuda_runtime.h>

#define B_ 64
#define T_ 800
#define J_ 50
#define D_ 200

constexpr int TPB  = 256;
constexpr int TBLK = 64;         // t-rows per block
constexpr int NBLK = 13;         // ceil(800/64)
constexpr int UP   = 204;        // u_s pitch (floats); 204%32=12 -> conflict-free B reads
constexpr int UP4  = 51;
constexpr int UROWS = 52;        // 50 u rows + w_h row (50) + zero row (51)
constexpr int AP   = 68;         // a_s pitch (floats); 68%32=4 -> conflict-free A reads
constexpr int JP   = 64;         // padded J (B n-range)
constexpr int STP  = 36;         // stage pitch; 36%32=4 -> conflict-free A reads
constexpr int STG  = 64 * STP;   // one stage buffer (floats) = 2304
constexpr int STG_OFF = UROWS * UP;   // 10608 floats

// scratch (no cudaMalloc allowed)
__device__ float2 g_cm[B_ * NBLK];
__device__ float  g_part[B_ * NBLK * D_];
__device__ __align__(16) float g_q2c[B_ * D_];

__device__ __forceinline__ float warpSum(float v) {
    #pragma unroll
    for (int o = 16; o > 0; o >>= 1) v += __shfl_xor_sync(0xffffffffu, v, o);
    return v;
}
__device__ __forceinline__ float warpMax(float v) {
    #pragma unroll
    for (int o = 16; o > 0; o >>= 1) v = fmaxf(v, __shfl_xor_sync(0xffffffffu, v, o));
    return v;
}
__device__ __forceinline__ void mma8(float d[4], const unsigned a[4], const unsigned b[2]) {
    asm("mma.sync.aligned.m16n8k8.row.col.f32.tf32.tf32.f32 "
        "{%0,%1,%2,%3}, {%4,%5,%6,%7}, {%8,%9}, {%0,%1,%2,%3};"
        : "+f"(d[0]), "+f"(d[1]), "+f"(d[2]), "+f"(d[3])
        : "r"(a[0]), "r"(a[1]), "r"(a[2]), "r"(a[3]), "r"(b[0]), "r"(b[1]));
}
__device__ __forceinline__ void split2(float x, unsigned& hi, unsigned& lo) {
    unsigned hh = __float_as_uint(x) & 0xffffe000u;
    hi = hh;
    lo = __float_as_uint(x - __uint_as_float(hh));
}

// c2q chunk: NTN n-tiles starting at ntBeg; result scaled by 1/w_hu[d]
template<int NTN>
__device__ __forceinline__ void c2q_chunk(
    int ntBeg, int dbase, const float* a_s, const float* u_s, const float* rwhu_s,
    int strip, int g, int tg,
    const float* hp0, const float* hp1, bool v0, bool v1,
    float* o0, float* o1)
{
    float dacc[NTN][4];
    #pragma unroll
    for (int q = 0; q < NTN; q++) {
        dacc[q][0] = 0.f; dacc[q][1] = 0.f; dacc[q][2] = 0.f; dacc[q][3] = 0.f;
    }
    const float* aR0 = a_s + (strip * 16 + g) * AP;
    const float* aR1 = aR0 + 8 * AP;
    #pragma unroll
    for (int ks = 0; ks < 8; ks++) {
        const int k0 = ks * 8 + tg;
        const int r0 = (k0 <= 51) ? k0 : 51;           // clamp to zero row
        const int r1 = (k0 + 4 <= 51) ? (k0 + 4) : 51;
        unsigned ah[4], al[4];
        split2(aR0[k0],     ah[0], al[0]);
        split2(aR1[k0],     ah[1], al[1]);
        split2(aR0[k0 + 4], ah[2], al[2]);
        split2(aR1[k0 + 4], ah[3], al[3]);
        const float* uk0 = u_s + r0 * UP + g;
        const float* uk1 = u_s + r1 * UP + g;
        #pragma unroll
        for (int q = 0; q < NTN; q++) {
            const int nb = dbase + (ntBeg + q) * 8;
            unsigned bh[2], bl[2];
            split2(uk0[nb], bh[0], bl[0]);
            split2(uk1[nb], bh[1], bl[1]);
            mma8(dacc[q], ah, bh);
            mma8(dacc[q], al, bh);
            mma8(dacc[q], ah, bl);
        }
    }
    #pragma unroll
    for (int q = 0; q < NTN; q++) {
        const int cc = dbase + (ntBeg + q) * 8 + 2 * tg;
        const float wx = rwhu_s[cc], wy = rwhu_s[cc + 1];
        if (v0) {
            float2 hv = *(const float2*)&hp0[cc];
            float2 c2 = make_float2(dacc[q][0] * wx, dacc[q][1] * wy);
            __stcs((float2*)(o0 + cc), hv);
            __stcs((float2*)(o0 + 200 + cc), c2);
            __stcs((float2*)(o0 + 400 + cc), make_float2(hv.x * c2.x, hv.y * c2.y));
        }
        if (v1) {
            float2 hv = *(const float2*)&hp1[cc];
            float2 c2 = make_float2(dacc[q][2] * wx, dacc[q][3] * wy);
            __stcs((float2*)(o1 + cc), hv);
            __stcs((float2*)(o1 + 200 + cc), c2);
            __stcs((float2*)(o1 + 400 + cc), make_float2(hv.x * c2.x, hv.y * c2.y));
        }
    }
}

// =====================================================================
// K1 (3xTF32, cp.async-pipelined A, w_hu folded into u', sh via col 50)
// smem: u' 42432 + stage 2*9216 + su/rwhu/m/es 1568 = 62432 B -> 3 CTA/SM
// =====================================================================
__global__ __launch_bounds__(TPB, 3) void bidaf_k1(
    const float* __restrict__ h, const float* __restrict__ u,
    const float* __restrict__ w_h, const float* __restrict__ b_h,
    const float* __restrict__ w_u, const float* __restrict__ b_u,
    const float* __restrict__ w_hu, const float* __restrict__ b_hu,
    float* __restrict__ out)
{
    extern __shared__ float sm[];
    float* u_s    = sm;                      // 52*204
    float* a_s    = sm + STG_OFF;            // 64*68, overlays stage after s-GEMM
    float* su_s   = sm + STG_OFF + 2 * STG;  // 64
    float* rwhu_s = su_s + JP;               // 200
    float* m_s    = rwhu_s + D_;             // 64
    float* es_s   = m_s + JP;                // 64

    const int b = blockIdx.y, c = blockIdx.x, t0 = c * TBLK;
    const int tid = threadIdx.x, warp = tid >> 5, lane = tid & 31;
    const int g = lane >> 2, tg = lane & 3;
    const int strip = warp & 3;     // m16 strip
    const int nh = warp >> 2;       // n-half

    const float4* u4g   = (const float4*)u;
    const float4* h4g   = (const float4*)h;
    const float4* whu4g = (const float4*)w_hu;
    const float4* wh4g  = (const float4*)w_h;
    float4* us4 = (float4*)u_s;
    const float* hb = h + (long)b * T_ * D_;
    const long hb4 = (long)b * T_ * 50;

    // ---- staging thread geometry ----
    const int srow = tid >> 3, sc = tid & 7;
    int tc0 = t0 + srow;      if (tc0 > T_ - 1) tc0 = T_ - 1;
    int tc1 = t0 + srow + 32; if (tc1 > T_ - 1) tc1 = T_ - 1;
    const unsigned sbase = (unsigned)__cvta_generic_to_shared(sm + STG_OFF);

    // ---- kick off rounds 0,1 immediately ----
    #pragma unroll
    for (int rd = 0; rd < 2; rd++) {
        if (sc < 8) {   // rounds 0,1 are full
            const float4* s0 = h4g + hb4 + (long)tc0 * 50 + rd * 8 + sc;
            const float4* s1 = h4g + hb4 + (long)tc1 * 50 + rd * 8 + sc;
            unsigned d0 = sbase + (unsigned)(rd * STG + srow * STP + sc * 4) * 4u;
            unsigned d1 = d0 + 32u * STP * 4u;
            asm volatile("cp.async.ca.shared.global [%0], [%1], 16;" :: "r"(d0), "l"(s0));
            asm volatile("cp.async.ca.shared.global [%0], [%1], 16;" :: "r"(d1), "l"(s1));
        }
        asm volatile("cp.async.commit_group;" ::: "memory");
    }

    // ---- u' tile: u'[j][d] = u[j][d]*w_hu[d]; row 50 = w_h; row 51 = 0 ----
    for (int idx = tid; idx < UROWS * UP4; idx += TPB) {
        int j = idx / UP4, k = idx - j * UP4;
        if (k < 50) {
            float4 v;
            if (j < J_) {
                float4 uv = u4g[(b * J_ + j) * 50 + k];
                float4 wv = whu4g[k];
                v = make_float4(uv.x * wv.x, uv.y * wv.y, uv.z * wv.z, uv.w * wv.w);
            } else if (j == 50) {
                v = wh4g[k];
            } else {
                v = make_float4(0.f, 0.f, 0.f, 0.f);
            }
            us4[j * UP4 + k] = v;
        }
    }
    if (tid < D_) {
        float w = w_hu[tid];
        rwhu_s[tid] = (w != 0.f) ? (1.0f / w) : 0.f;
    }
    const float bias = b_h[0] + b_u[0] + b_hu[0];

    // ---- su_s[j] from GLOBAL u (u_s holds u'); su[>=50] = 0 ----
    const float4* wu4 = (const float4*)w_u;
    for (int j = warp; j < JP; j += 8) {
        if (j < J_) {
            const float4* ug = u4g + (long)(b * J_ + j) * 50;
            float4 a1 = ug[lane], w1 = wu4[lane];
            float acc = a1.x * w1.x + a1.y * w1.y + a1.z * w1.z + a1.w * w1.w;
            if (lane < 18) {
                float4 a2 = ug[32 + lane], w2 = wu4[32 + lane];
                acc += a2.x * w2.x + a2.y * w2.y + a2.z * w2.z + a2.w * w2.w;
            }
            acc = warpSum(acc);
            if (lane == 0) su_s[j] = acc + bias;
        } else if (lane == 0) su_s[j] = 0.f;
    }
    __syncthreads();   // u', su, rwhu ready

    // ---- s-GEMM: A = raw h (cp.async staged), B = u' ----
    float accS[4][4];
    #pragma unroll
    for (int nt = 0; nt < 4; nt++) {
        accS[nt][0] = 0.f; accS[nt][1] = 0.f; accS[nt][2] = 0.f; accS[nt][3] = 0.f;
    }
    const float* urp[4];
    #pragma unroll
    for (int nt = 0; nt < 4; nt++) {
        int br = nh * 32 + nt * 8 + g;
        if (br > 51) br = 51;          // zero row
        urp[nt] = u_s + br * UP;
    }
    const float* stA = sm + STG_OFF + (strip * 16 + g) * STP;

    #pragma unroll 1
    for (int rd = 0; rd < 7; rd++) {
        asm volatile("cp.async.wait_group 1;" ::: "memory");
        __syncthreads();                        // round rd resident everywhere
        const float* s0r = stA + (rd & 1) * STG;
        const float* s1r = s0r + 8 * STP;
        const int nks = (rd < 6) ? 4 : 1;
        for (int ksl = 0; ksl < nks; ksl++) {
            const int c0 = ksl * 8 + tg, c1 = c0 + 4;
            const int kd0 = rd * 32 + c0, kd1 = rd * 32 + c1;
            unsigned ah[4], al[4];
            split2(s0r[c0], ah[0], al[0]);
            split2(s1r[c0], ah[1], al[1]);
            split2(s0r[c1], ah[2], al[2]);
            split2(s1r[c1], ah[3], al[3]);
            #pragma unroll
            for (int nt = 0; nt < 4; nt++) {
                const float* ur = urp[nt];
                unsigned bh[2], bl[2];
                split2(ur[kd0], bh[0], bl[0]);
                split2(ur[kd1], bh[1], bl[1]);
                mma8(accS[nt], ah, bh);
                mma8(accS[nt], al, bh);
                mma8(accS[nt], ah, bl);
            }
        }
        __syncthreads();                        // buffer rd&1 free
        if (rd + 2 < 7) {
            const int rn = rd + 2;
            const int nf4 = (rn < 6) ? 8 : 2;
            if (sc < nf4) {
                const float4* s0 = h4g + hb4 + (long)tc0 * 50 + rn * 8 + sc;
                const float4* s1 = h4g + hb4 + (long)tc1 * 50 + rn * 8 + sc;
                unsigned d0 = sbase + (unsigned)((rd & 1) * STG + srow * STP + sc * 4) * 4u;
                unsigned d1 = d0 + 32u * STP * 4u;
                asm volatile("cp.async.ca.shared.global [%0], [%1], 16;" :: "r"(d0), "l"(s0));
                asm volatile("cp.async.ca.shared.global [%0], [%1], 16;" :: "r"(d1), "l"(s1));
            }
            asm volatile("cp.async.commit_group;" ::: "memory");
        } else {
            asm volatile("cp.async.commit_group;" ::: "memory");   // keep group count
        }
    }

    // ---- s-GEMM epilogue: s' = acc + su (col 50 keeps sh; su[>=50]=0) ----
    {
        float* sr0 = a_s + (strip * 16 + g) * AP;
        float* sr1 = sr0 + 8 * AP;
        #pragma unroll
        for (int nt = 0; nt < 4; nt++) {
            const int cc = nh * 32 + nt * 8 + 2 * tg;
            float2 su2 = *(const float2*)&su_s[cc];
            *(float2*)&sr0[cc] = make_float2(accS[nt][0] + su2.x, accS[nt][1] + su2.y);
            *(float2*)&sr1[cc] = make_float2(accS[nt][2] + su2.x, accS[nt][3] + su2.y);
        }
    }
    __syncthreads();

    // ---- softmax: 4 threads/row; col 50 = sh, cols >=50 masked to 0 ----
    {
        const int row = tid >> 2, q = tid & 3;
        float4* ar = (float4*)&a_s[row * AP + q * 16];
        float4 v0 = ar[0], v1 = ar[1], v2 = ar[2], v3 = ar[3];
        float shv;
        if (q == 3) {
            shv = v0.z;                        // col 50
            v0.z = -1e30f; v0.w = -1e30f;
            v1 = make_float4(-1e30f, -1e30f, -1e30f, -1e30f);
            v2 = v1; v3 = v1;
        } else {
            shv = a_s[row * AP + 50];
        }
        float mx = fmaxf(fmaxf(fmaxf(v0.x, v0.y), fmaxf(v0.z, v0.w)),
                   fmaxf(fmaxf(fmaxf(v1.x, v1.y), fmaxf(v1.z, v1.w)),
                   fmaxf(fmaxf(fmaxf(v2.x, v2.y), fmaxf(v2.z, v2.w)),
                         fmaxf(fmaxf(v3.x, v3.y), fmaxf(v3.z, v3.w)))));
        mx = fmaxf(mx, __shfl_xor_sync(0xffffffffu, mx, 1));
        mx = fmaxf(mx, __shfl_xor_sync(0xffffffffu, mx, 2));
        v0.x = __expf(v0.x - mx); v0.y = __expf(v0.y - mx);
        v0.z = __expf(v0.z - mx); v0.w = __expf(v0.w - mx);
        v1.x = __expf(v1.x - mx); v1.y = __expf(v1.y - mx);
        v1.z = __expf(v1.z - mx); v1.w = __expf(v1.w - mx);
        v2.x = __expf(v2.x - mx); v2.y = __expf(v2.y - mx);
        v2.z = __expf(v2.z - mx); v2.w = __expf(v2.w - mx);
        v3.x = __expf(v3.x - mx); v3.y = __expf(v3.y - mx);
        v3.z = __expf(v3.z - mx); v3.w = __expf(v3.w - mx);
        float s = (v0.x + v0.y + v0.z + v0.w) + (v1.x + v1.y + v1.z + v1.w)
                + (v2.x + v2.y + v2.z + v2.w) + (v3.x + v3.y + v3.z + v3.w);
        s += __shfl_xor_sync(0xffffffffu, s, 1);
        s += __shfl_xor_sync(0xffffffffu, s, 2);
        const float inv = 1.f / s;
        v0.x *= inv; v0.y *= inv; v0.z *= inv; v0.w *= inv;
        v1.x *= inv; v1.y *= inv; v1.z *= inv; v1.w *= inv;
        v2.x *= inv; v2.y *= inv; v2.z *= inv; v2.w *= inv;
        v3.x *= inv; v3.y *= inv; v3.z *= inv; v3.w *= inv;
        ar[0] = v0; ar[1] = v1; ar[2] = v2; ar[3] = v3;   // masked cols -> 0
        if (q == 0) m_s[row] = (t0 + row < T_) ? (mx + shv) : -3.0e38f;
    }
    __syncthreads();

    // ---- warp 0: chunk max/expsum over 64 rows ----
    if (warp == 0) {
        float m0 = m_s[lane], m1 = m_s[lane + 32];
        float mc = warpMax(fmaxf(m0, m1));
        float e0 = __expf(m0 - mc), e1 = __expf(m1 - mc);
        float sc2 = warpSum(e0 + e1);
        es_s[lane] = e0; es_s[lane + 32] = e1;
        if (lane == 0) g_cm[b * NBLK + c] = make_float2(mc, sc2);
    }

    // ---- c2q GEMM + fused epilogue (result scaled by 1/w_hu) ----
    {
        const int dbase = nh * 104;      // half0: 13 tiles, half1: 12 tiles
        const int tr0 = t0 + strip * 16 + g, tr1 = tr0 + 8;
        const bool v0 = tr0 < T_, v1 = tr1 < T_;
        const float* hp0 = hb + (long)(v0 ? tr0 : 0) * D_;
        const float* hp1 = hb + (long)(v1 ? tr1 : 0) * D_;
        float* o0 = out + (long)(b * T_ + (v0 ? tr0 : 0)) * (4 * D_);
        float* o1 = out + (long)(b * T_ + (v1 ? tr1 : 0)) * (4 * D_);
        if (nh == 0) {
            c2q_chunk<7>(0, dbase, a_s, u_s, rwhu_s, strip, g, tg, hp0, hp1, v0, v1, o0, o1);
            c2q_chunk<6>(7, dbase, a_s, u_s, rwhu_s, strip, g, tg, hp0, hp1, v0, v1, o0, o1);
        } else {
            c2q_chunk<7>(0, dbase, a_s, u_s, rwhu_s, strip, g, tg, hp0, hp1, v0, v1, o0, o1);
            c2q_chunk<5>(7, dbase, a_s, u_s, rwhu_s, strip, g, tg, hp0, hp1, v0, v1, o0, o1);
        }
    }

    // ---- chunk-local q2c partial ----
    __syncthreads();
    if (tid < D_) {
        const int RV = (T_ - t0 < TBLK) ? (T_ - t0) : TBLK;
        const float* hp = hb + (long)t0 * D_ + tid;
        float a0 = 0.f, a1 = 0.f, a2 = 0.f, a3 = 0.f;
        for (int r = 0; r < RV; r += 4) {
            a0 += es_s[r]     * hp[r * D_];
            a1 += es_s[r + 1] * hp[(r + 1) * D_];
            a2 += es_s[r + 2] * hp[(r + 2) * D_];
            a3 += es_s[r + 3] * hp[(r + 3) * D_];
        }
        g_part[(b * NBLK + c) * D_ + tid] = (a0 + a1) + (a2 + a3);
    }
}

// =====================================================================
// K2: per-batch combine -> g_q2c
// =====================================================================
__global__ __launch_bounds__(256) void bidaf_k2()
{
    __shared__ float ws[32];
    __shared__ float Ss;
    const int b = blockIdx.x, tid = threadIdx.x;
    if (tid < 32) {
        float2 cm = (tid < NBLK) ? g_cm[b * NBLK + tid] : make_float2(-3.0e38f, 0.f);
        float M = warpMax(cm.x);
        float e = (tid < NBLK) ? __expf(cm.x - M) : 0.f;
        float S = warpSum(e * cm.y);
        ws[tid] = e;
        if (tid == 0) Ss = S;
    }
    __syncthreads();
    if (tid < D_) {
        float acc = 0.f;
        #pragma unroll
        for (int c2 = 0; c2 < NBLK; c2++)
            acc += ws[c2] * g_part[(b * NBLK + c2) * D_ + tid];
        g_q2c[b * D_ + tid] = acc / Ss;
    }
}

// =====================================================================
// K3: out[b,t,600:800] = h * q2c
// =====================================================================
__global__ __launch_bounds__(256) void bidaf_k3(const float* __restrict__ h,
                                                float* __restrict__ out)
{
    long idx = (long)blockIdx.x * 256 + threadIdx.x;   // float4 index
    if (idx >= (long)B_ * T_ * 50) return;
    int d4 = (int)(idx % 50);
    long bt = idx / 50;
    int b = (int)(bt / T_);
    float4 hv = __ldg(((const float4*)h) + idx);
    float4 q  = __ldg(((const float4*)g_q2c) + b * 50 + d4);
    __stcs(((float4*)out) + bt * 200 + 150 + d4,
           make_float4(hv.x * q.x, hv.y * q.y, hv.z * q.z, hv.w * q.w));
}

// =====================================================================
extern "C" void kernel_launch(void* const* d_in, const int* in_sizes, int n_in,
                              void* d_out, int out_size)
{
    const float* h    = (const float*)d_in[0];
    const float* u    = (const float*)d_in[1];
    const float* w_h  = (const float*)d_in[2];
    const float* b_h  = (const float*)d_in[3];
    const float* w_u  = (const float*)d_in[4];
    const float* b_u  = (const float*)d_in[5];
    const float* w_hu = (const float*)d_in[6];
    const float* b_hu = (const float*)d_in[7];
    float* out = (float*)d_out;

    // u' + 2 stage buffers + su + rwhu + m + es
    constexpr int SMEM1 = (STG_OFF + 2 * STG + JP + D_ + JP + JP) * 4;  // 62432
    cudaFuncSetAttribute(bidaf_k1, cudaFuncAttributeMaxDynamicSharedMemorySize, SMEM1);

    bidaf_k1<<<dim3(NBLK, B_), TPB, SMEM1>>>(h, u, w_h, b_h, w_u, b_u, w_hu, b_hu, out);
    bidaf_k2<<<B_, 256>>>();
    int total4 = B_ * T_ * 50;
    bidaf_k3<<<(total4 + 255) / 256, 256>>>(h, out);
}